// round 3
// baseline (speedup 1.0000x reference)
#include <cuda_runtime.h>
#include <math.h>

#define IN_DIM 256
#define HID 128
#define OUTD 64
#define NMAX 50176
#define EMAX 800000

// ---------------- scratch (static device globals; no allocation) ----------------
__device__ int g_is64;                 // 1 if edge_index is int64, 0 if int32
__device__ __align__(16) int   g_src[EMAX];
__device__ __align__(16) int   g_dst[EMAX];
__device__ __align__(16) int   g_cnt[NMAX];
__device__ __align__(16) int   g_rowptr[NMAX + 1];
__device__ __align__(16) int   g_cursor[NMAX];
__device__ __align__(16) int   g_col[EMAX];
__device__ __align__(16) float g_dinv[NMAX];
__device__ __align__(16) float g_t1[(size_t)NMAX * HID];   // (x@W1)*dinv[row]
__device__ __align__(16) float g_h1[(size_t)NMAX * HID];   // relu(gcn1)
__device__ __align__(16) float g_t2[(size_t)NMAX * OUTD];  // (h1@W2)*dinv[row]

// ---------------- edge width detection + conversion ----------------
// If the buffer is int64 little-endian with values < 2^31, every odd 32-bit
// word is zero. Random int32 edge data (values 0..n-1, mostly nonzero) cannot
// alias this over 256 samples.
__global__ void detect_kernel(const int* __restrict__ raw, int E) {
    __shared__ int s_nz;
    if (threadIdx.x == 0) s_nz = 0;
    __syncthreads();
    int i = threadIdx.x;   // 256 threads, sample first 256 candidate high-words
    if (i < E && raw[2 * i + 1] != 0) atomicOr(&s_nz, 1);
    __syncthreads();
    if (threadIdx.x == 0) g_is64 = (s_nz == 0) ? 1 : 0;
}

__global__ void zero_cnt_kernel(int n) {
    int i = blockIdx.x * blockDim.x + threadIdx.x;
    if (i < n) g_cnt[i] = 0;
}

// convert edges to int32 src/dst arrays + histogram of dst
__global__ void convert_hist_kernel(const int* __restrict__ raw, int E) {
    int i = blockIdx.x * blockDim.x + threadIdx.x;
    if (i >= E) return;
    int s, d;
    if (g_is64) {
        s = raw[2 * i];
        d = raw[2 * E + 2 * i];
    } else {
        s = raw[i];
        d = raw[E + i];
    }
    g_src[i] = s;
    g_dst[i] = d;
    atomicAdd(&g_cnt[d], 1);
}

// single-block exclusive scan of g_cnt -> g_rowptr (+g_cursor copy), and dinv
__global__ void scan_kernel(int n) {
    __shared__ int ssum[1024];
    int t = threadIdx.x;
    int chunk = (n + 1023) / 1024;
    int beg = t * chunk;
    int end = min(beg + chunk, n);
    int s = 0;
    for (int i = beg; i < end; i++) s += g_cnt[i];
    ssum[t] = s;
    __syncthreads();
    for (int off = 1; off < 1024; off <<= 1) {
        int v = (t >= off) ? ssum[t - off] : 0;
        __syncthreads();
        ssum[t] += v;
        __syncthreads();
    }
    int run = (t == 0) ? 0 : ssum[t - 1];
    for (int i = beg; i < end; i++) {
        g_rowptr[i] = run;
        g_cursor[i] = run;
        g_dinv[i]   = rsqrtf((float)g_cnt[i] + 1.0f);  // +1 self loop
        run += g_cnt[i];
    }
    if (t == 1023) g_rowptr[n] = ssum[1023];
}

__global__ void scatter_kernel(int E) {
    int i = blockIdx.x * blockDim.x + threadIdx.x;
    if (i < E) {
        int pos = atomicAdd(&g_cursor[g_dst[i]], 1);
        g_col[pos] = g_src[i];
    }
}

// ---------------- tiled SIMT fp32 GEMM, epilogue: C[row,:] = acc * dinv[row] ----------------
// LAYER==0: A = A_in (x), C = g_t1.  LAYER==1: A = g_h1, C = g_t2.
// Assumes N == BN (single column block), K % BK == 0.
template <int BM, int BN, int BK, int TM, int TN, int LAYER>
__global__ void gemm_scaled(const float* __restrict__ A_in, const float* __restrict__ B,
                            int M, int K, int N) {
    const float* __restrict__ A = (LAYER == 0) ? A_in : g_h1;
    float* __restrict__ C       = (LAYER == 0) ? g_t1 : g_t2;

    constexpr int THREADS = (BM / TM) * (BN / TN);
    __shared__ float As[BK][BM + 4];
    __shared__ float Bs[BK][BN + 4];

    int tid = threadIdx.x;
    int tx = tid % (BN / TN);
    int ty = tid / (BN / TN);
    int row0 = blockIdx.x * BM;

    float acc[TM][TN];
#pragma unroll
    for (int i = 0; i < TM; i++)
#pragma unroll
        for (int j = 0; j < TN; j++) acc[i][j] = 0.0f;

    for (int kt = 0; kt < K; kt += BK) {
        constexpr int A4 = BM * BK / 4;
#pragma unroll
        for (int l = tid; l < A4; l += THREADS) {
            int r = l / (BK / 4);
            int kq = l % (BK / 4);
            float4 v = make_float4(0.f, 0.f, 0.f, 0.f);
            int row = row0 + r;
            if (row < M) v = *(const float4*)&A[(size_t)row * K + kt + kq * 4];
            As[kq * 4 + 0][r] = v.x;
            As[kq * 4 + 1][r] = v.y;
            As[kq * 4 + 2][r] = v.z;
            As[kq * 4 + 3][r] = v.w;
        }
        constexpr int B4 = BK * BN / 4;
#pragma unroll
        for (int l = tid; l < B4; l += THREADS) {
            int k = l / (BN / 4);
            int cq = l % (BN / 4);
            *(float4*)&Bs[k][cq * 4] = *(const float4*)&B[(size_t)(kt + k) * N + cq * 4];
        }
        __syncthreads();
#pragma unroll
        for (int k = 0; k < BK; k++) {
            float ra[TM], rb[TN];
#pragma unroll
            for (int i = 0; i < TM; i++) ra[i] = As[k][ty * TM + i];
#pragma unroll
            for (int j = 0; j < TN; j++) rb[j] = Bs[k][tx * TN + j];
#pragma unroll
            for (int i = 0; i < TM; i++)
#pragma unroll
                for (int j = 0; j < TN; j++) acc[i][j] = fmaf(ra[i], rb[j], acc[i][j]);
        }
        __syncthreads();
    }

#pragma unroll
    for (int i = 0; i < TM; i++) {
        int row = row0 + ty * TM + i;
        if (row < M) {
            float di = g_dinv[row];
#pragma unroll
            for (int j = 0; j < TN; j += 4) {
                float4 v;
                v.x = acc[i][j + 0] * di;
                v.y = acc[i][j + 1] * di;
                v.z = acc[i][j + 2] * di;
                v.w = acc[i][j + 3] * di;
                *(float4*)&C[(size_t)row * N + tx * TN + j] = v;
            }
        }
    }
}

// ---------------- layer-1 aggregation: warp per node, 128 features ----------------
__global__ void agg1_kernel(const float* __restrict__ b1, int n) {
    int w = (blockIdx.x * blockDim.x + threadIdx.x) >> 5;
    int lane = threadIdx.x & 31;
    if (w >= n) return;
    const float4* g = (const float4*)g_t1;
    float4 acc = g[(size_t)w * 32 + lane];  // self loop
    int e = g_rowptr[w], end = g_rowptr[w + 1];
    for (; e + 4 <= end; e += 4) {
        int s0 = g_col[e], s1 = g_col[e + 1], s2 = g_col[e + 2], s3 = g_col[e + 3];
        float4 v0 = g[(size_t)s0 * 32 + lane];
        float4 v1 = g[(size_t)s1 * 32 + lane];
        float4 v2 = g[(size_t)s2 * 32 + lane];
        float4 v3 = g[(size_t)s3 * 32 + lane];
        acc.x += v0.x + v1.x + v2.x + v3.x;
        acc.y += v0.y + v1.y + v2.y + v3.y;
        acc.z += v0.z + v1.z + v2.z + v3.z;
        acc.w += v0.w + v1.w + v2.w + v3.w;
    }
    for (; e < end; e++) {
        int s = g_col[e];
        float4 v = g[(size_t)s * 32 + lane];
        acc.x += v.x; acc.y += v.y; acc.z += v.z; acc.w += v.w;
    }
    float di = g_dinv[w];
    float4 b = ((const float4*)b1)[lane];
    float4 r;
    r.x = fmaxf(fmaf(acc.x, di, b.x), 0.f);
    r.y = fmaxf(fmaf(acc.y, di, b.y), 0.f);
    r.z = fmaxf(fmaf(acc.z, di, b.z), 0.f);
    r.w = fmaxf(fmaf(acc.w, di, b.w), 0.f);
    ((float4*)g_h1)[(size_t)w * 32 + lane] = r;
}

// ---------------- layer-2 aggregation + rule head + log_softmax ----------------
__global__ void agg2_final_kernel(const float* __restrict__ b2,
                                  const float* __restrict__ We,
                                  const float* __restrict__ be,
                                  const float* __restrict__ Wg,
                                  const float* __restrict__ bg,
                                  const float* __restrict__ rw,
                                  float* __restrict__ out, int n) {
    int w = (blockIdx.x * blockDim.x + threadIdx.x) >> 5;
    int lane = threadIdx.x & 31;
    if (w >= n) return;
    const float2* g = (const float2*)g_t2;
    float2 acc = g[(size_t)w * 32 + lane];  // self loop
    int e = g_rowptr[w], end = g_rowptr[w + 1];
    for (; e + 4 <= end; e += 4) {
        int s0 = g_col[e], s1 = g_col[e + 1], s2 = g_col[e + 2], s3 = g_col[e + 3];
        float2 v0 = g[(size_t)s0 * 32 + lane];
        float2 v1 = g[(size_t)s1 * 32 + lane];
        float2 v2 = g[(size_t)s2 * 32 + lane];
        float2 v3 = g[(size_t)s3 * 32 + lane];
        acc.x += v0.x + v1.x + v2.x + v3.x;
        acc.y += v0.y + v1.y + v2.y + v3.y;
    }
    for (; e < end; e++) {
        int s = g_col[e];
        float2 v = g[(size_t)s * 32 + lane];
        acc.x += v.x; acc.y += v.y;
    }
    float di = g_dinv[w];
    float2 b = ((const float2*)b2)[lane];
    float hx = fmaf(acc.x, di, b.x);
    float hy = fmaf(acc.y, di, b.y);

    // rule_out = h @ We + be (We: [64,3] row-major); lane holds cols 2*lane, 2*lane+1
    int c0 = 2 * lane;
    float p0 = hx * We[c0 * 3 + 0] + hy * We[c0 * 3 + 3];
    float p1 = hx * We[c0 * 3 + 1] + hy * We[c0 * 3 + 4];
    float p2 = hx * We[c0 * 3 + 2] + hy * We[c0 * 3 + 5];
#pragma unroll
    for (int off = 16; off; off >>= 1) {
        p0 += __shfl_xor_sync(0xffffffff, p0, off);
        p1 += __shfl_xor_sync(0xffffffff, p1, off);
        p2 += __shfl_xor_sync(0xffffffff, p2, off);
    }
    float r0 = p0 + be[0], r1 = p1 + be[1], r2 = p2 + be[2];
    float z = r0 * Wg[0] + r1 * Wg[1] + r2 * Wg[2] + bg[0];
    float gate = 1.0f / (1.0f + expf(-z));
    float add = gate * rw[0];
    hx += add;
    hy += add;

    // log_softmax over the 64 features
    float m = fmaxf(hx, hy);
#pragma unroll
    for (int off = 16; off; off >>= 1) m = fmaxf(m, __shfl_xor_sync(0xffffffff, m, off));
    float se = expf(hx - m) + expf(hy - m);
#pragma unroll
    for (int off = 16; off; off >>= 1) se += __shfl_xor_sync(0xffffffff, se, off);
    float ls = logf(se);

    float2 o;
    o.x = hx - m - ls;
    o.y = hy - m - ls;
    ((float2*)out)[(size_t)w * 32 + lane] = o;
}

// ---------------- launch ----------------
extern "C" void kernel_launch(void* const* d_in, const int* in_sizes, int n_in,
                              void* d_out, int out_size) {
    const float* x   = (const float*)d_in[0];
    const int*   ei  = (const int*)d_in[1];   // int32 or int64 raw words; detected on device
    // d_in[2] = rules (unused by the math)
    const float* W1 = (const float*)d_in[3];
    const float* b1 = (const float*)d_in[4];
    const float* W2 = (const float*)d_in[5];
    const float* b2 = (const float*)d_in[6];
    const float* We = (const float*)d_in[7];
    const float* be = (const float*)d_in[8];
    const float* Wg = (const float*)d_in[9];
    const float* bg = (const float*)d_in[10];
    const float* rw = (const float*)d_in[11];

    int n = in_sizes[0] / IN_DIM;
    int E = in_sizes[1] / 2;

    // CSR build (shared by both layers)
    detect_kernel<<<1, 256>>>(ei, E);
    zero_cnt_kernel<<<(n + 255) / 256, 256>>>(n);
    convert_hist_kernel<<<(E + 255) / 256, 256>>>(ei, E);
    scan_kernel<<<1, 1024>>>(n);
    scatter_kernel<<<(E + 255) / 256, 256>>>(E);

    // layer 1
    gemm_scaled<128, 128, 16, 8, 8, 0><<<(n + 127) / 128, 256>>>(x, W1, n, IN_DIM, HID);
    agg1_kernel<<<(n * 32 + 255) / 256, 256>>>(b1, n);

    // layer 2
    gemm_scaled<128, 64, 16, 8, 8, 1><<<(n + 127) / 128, 128>>>(nullptr, W2, n, HID, OUTD);

    // aggregation + rule head + log_softmax fused
    agg2_final_kernel<<<(n * 32 + 255) / 256, 256>>>(b2, We, be, Wg, bg, rw, (float*)d_out, n);
}

// round 4
// speedup vs baseline: 1.4316x; 1.4316x over previous
#include <cuda_runtime.h>
#include <math.h>

#define IN_DIM 256
#define HID 128
#define OUTD 64
#define NMAX 50176
#define EMAX 800000

// ---------------- scratch (static device globals; no allocation) ----------------
__device__ int g_is64;                 // 1 if edge_index is int64, 0 if int32
__device__ __align__(16) int   g_src[EMAX];
__device__ __align__(16) int   g_dst[EMAX];
__device__ __align__(16) int   g_cnt[NMAX];
__device__ __align__(16) int   g_locpre[NMAX];   // block-local exclusive prefix
__device__ __align__(16) int   g_bsum[256];      // per-block sums
__device__ __align__(16) int   g_boff[256];      // scanned block offsets
__device__ __align__(16) int   g_rowptr[NMAX + 1];
__device__ __align__(16) int   g_cursor[NMAX];
__device__ __align__(16) int   g_col[EMAX];
__device__ __align__(16) float g_dinv[NMAX];
__device__ __align__(16) float g_t1[(size_t)NMAX * HID];   // (x@W1)*dinv[row]
__device__ __align__(16) float g_h1[(size_t)NMAX * HID];   // relu(gcn1)
__device__ __align__(16) float g_t2[(size_t)NMAX * OUTD];  // (h1@W2)*dinv[row]

// ---------------- edge width detection ----------------
// int64 little-endian with values < 2^31 => every odd 32-bit word is zero.
__global__ void detect_kernel(const int* __restrict__ raw, int E) {
    __shared__ int s_nz;
    if (threadIdx.x == 0) s_nz = 0;
    __syncthreads();
    int i = threadIdx.x;
    if (i < E && raw[2 * i + 1] != 0) atomicOr(&s_nz, 1);
    __syncthreads();
    if (threadIdx.x == 0) g_is64 = (s_nz == 0) ? 1 : 0;
}

__global__ void zero_cnt_kernel(int n) {
    int i = blockIdx.x * blockDim.x + threadIdx.x;
    if (i < n) g_cnt[i] = 0;
}

// convert edges to int32 src/dst arrays + histogram of dst
__global__ void convert_hist_kernel(const int* __restrict__ raw, int E) {
    int i = blockIdx.x * blockDim.x + threadIdx.x;
    if (i >= E) return;
    int s, d;
    if (g_is64) {
        s = raw[2 * i];
        d = raw[2 * E + 2 * i];
    } else {
        s = raw[i];
        d = raw[E + i];
    }
    g_src[i] = s;
    g_dst[i] = d;
    atomicAdd(&g_cnt[d], 1);
}

// ---------------- multi-block exclusive scan (3 phases) ----------------
// Phase 1: per-block exclusive scan of g_cnt (256 elems/block) -> g_locpre, g_bsum
__global__ void scan_phase1(int n) {
    __shared__ int sh[256];
    int t = threadIdx.x;
    int i = blockIdx.x * 256 + t;
    int v = (i < n) ? g_cnt[i] : 0;
    sh[t] = v;
    __syncthreads();
    // inclusive Hillis-Steele
#pragma unroll
    for (int off = 1; off < 256; off <<= 1) {
        int u = (t >= off) ? sh[t - off] : 0;
        __syncthreads();
        sh[t] += u;
        __syncthreads();
    }
    if (i < n) g_locpre[i] = sh[t] - v;   // exclusive
    if (t == 255) g_bsum[blockIdx.x] = sh[255];
}

// Phase 2: single block scans the block sums (<=256 of them) -> g_boff (exclusive)
__global__ void scan_phase2(int nb) {
    __shared__ int sh[256];
    int t = threadIdx.x;
    int v = (t < nb) ? g_bsum[t] : 0;
    sh[t] = v;
    __syncthreads();
#pragma unroll
    for (int off = 1; off < 256; off <<= 1) {
        int u = (t >= off) ? sh[t - off] : 0;
        __syncthreads();
        sh[t] += u;
        __syncthreads();
    }
    if (t < nb) g_boff[t] = sh[t] - v;
}

// Phase 3: combine; fill rowptr/cursor/dinv
__global__ void scan_phase3(int n, int E) {
    int i = blockIdx.x * blockDim.x + threadIdx.x;
    if (i < n) {
        int rp = g_boff[i >> 8] + g_locpre[i];
        g_rowptr[i] = rp;
        g_cursor[i] = rp;
        g_dinv[i]   = rsqrtf((float)g_cnt[i] + 1.0f);  // +1 self loop
    }
    if (i == 0) g_rowptr[n] = E;
}

__global__ void scatter_kernel(int E) {
    int i = blockIdx.x * blockDim.x + threadIdx.x;
    if (i < E) {
        int pos = atomicAdd(&g_cursor[g_dst[i]], 1);
        g_col[pos] = g_src[i];
    }
}

// ---------------- tiled SIMT fp32 GEMM, epilogue: C[row,:] = acc * dinv[row] ----------------
// LAYER==0: A = A_in (x), C = g_t1.  LAYER==1: A = g_h1, C = g_t2.
template <int BM, int BN, int BK, int TM, int TN, int LAYER>
__global__ void gemm_scaled(const float* __restrict__ A_in, const float* __restrict__ B,
                            int M, int K, int N) {
    const float* __restrict__ A = (LAYER == 0) ? A_in : g_h1;
    float* __restrict__ C       = (LAYER == 0) ? g_t1 : g_t2;

    constexpr int THREADS = (BM / TM) * (BN / TN);
    __shared__ float As[BK][BM + 4];
    __shared__ float Bs[BK][BN + 4];

    int tid = threadIdx.x;
    int tx = tid % (BN / TN);
    int ty = tid / (BN / TN);
    int row0 = blockIdx.x * BM;

    float acc[TM][TN];
#pragma unroll
    for (int i = 0; i < TM; i++)
#pragma unroll
        for (int j = 0; j < TN; j++) acc[i][j] = 0.0f;

    for (int kt = 0; kt < K; kt += BK) {
        constexpr int A4 = BM * BK / 4;
#pragma unroll
        for (int l = tid; l < A4; l += THREADS) {
            int r = l / (BK / 4);
            int kq = l % (BK / 4);
            float4 v = make_float4(0.f, 0.f, 0.f, 0.f);
            int row = row0 + r;
            if (row < M) v = *(const float4*)&A[(size_t)row * K + kt + kq * 4];
            As[kq * 4 + 0][r] = v.x;
            As[kq * 4 + 1][r] = v.y;
            As[kq * 4 + 2][r] = v.z;
            As[kq * 4 + 3][r] = v.w;
        }
        constexpr int B4 = BK * BN / 4;
#pragma unroll
        for (int l = tid; l < B4; l += THREADS) {
            int k = l / (BN / 4);
            int cq = l % (BN / 4);
            *(float4*)&Bs[k][cq * 4] = *(const float4*)&B[(size_t)(kt + k) * N + cq * 4];
        }
        __syncthreads();
#pragma unroll
        for (int k = 0; k < BK; k++) {
            float ra[TM], rb[TN];
#pragma unroll
            for (int i = 0; i < TM; i++) ra[i] = As[k][ty * TM + i];
#pragma unroll
            for (int j = 0; j < TN; j++) rb[j] = Bs[k][tx * TN + j];
#pragma unroll
            for (int i = 0; i < TM; i++)
#pragma unroll
                for (int j = 0; j < TN; j++) acc[i][j] = fmaf(ra[i], rb[j], acc[i][j]);
        }
        __syncthreads();
    }

#pragma unroll
    for (int i = 0; i < TM; i++) {
        int row = row0 + ty * TM + i;
        if (row < M) {
            float di = g_dinv[row];
#pragma unroll
            for (int j = 0; j < TN; j += 4) {
                float4 v;
                v.x = acc[i][j + 0] * di;
                v.y = acc[i][j + 1] * di;
                v.z = acc[i][j + 2] * di;
                v.w = acc[i][j + 3] * di;
                *(float4*)&C[(size_t)row * N + tx * TN + j] = v;
            }
        }
    }
}

// ---------------- layer-1 aggregation: warp per node, 128 features ----------------
__global__ void agg1_kernel(const float* __restrict__ b1, int n) {
    int w = (blockIdx.x * blockDim.x + threadIdx.x) >> 5;
    int lane = threadIdx.x & 31;
    if (w >= n) return;
    const float4* g = (const float4*)g_t1;
    float4 acc = g[(size_t)w * 32 + lane];  // self loop
    int e = g_rowptr[w], end = g_rowptr[w + 1];
    for (; e + 4 <= end; e += 4) {
        int s0 = g_col[e], s1 = g_col[e + 1], s2 = g_col[e + 2], s3 = g_col[e + 3];
        float4 v0 = g[(size_t)s0 * 32 + lane];
        float4 v1 = g[(size_t)s1 * 32 + lane];
        float4 v2 = g[(size_t)s2 * 32 + lane];
        float4 v3 = g[(size_t)s3 * 32 + lane];
        acc.x += v0.x + v1.x + v2.x + v3.x;
        acc.y += v0.y + v1.y + v2.y + v3.y;
        acc.z += v0.z + v1.z + v2.z + v3.z;
        acc.w += v0.w + v1.w + v2.w + v3.w;
    }
    for (; e < end; e++) {
        int s = g_col[e];
        float4 v = g[(size_t)s * 32 + lane];
        acc.x += v.x; acc.y += v.y; acc.z += v.z; acc.w += v.w;
    }
    float di = g_dinv[w];
    float4 b = ((const float4*)b1)[lane];
    float4 r;
    r.x = fmaxf(fmaf(acc.x, di, b.x), 0.f);
    r.y = fmaxf(fmaf(acc.y, di, b.y), 0.f);
    r.z = fmaxf(fmaf(acc.z, di, b.z), 0.f);
    r.w = fmaxf(fmaf(acc.w, di, b.w), 0.f);
    ((float4*)g_h1)[(size_t)w * 32 + lane] = r;
}

// ---------------- layer-2 aggregation + rule head + log_softmax ----------------
__global__ void agg2_final_kernel(const float* __restrict__ b2,
                                  const float* __restrict__ We,
                                  const float* __restrict__ be,
                                  const float* __restrict__ Wg,
                                  const float* __restrict__ bg,
                                  const float* __restrict__ rw,
                                  float* __restrict__ out, int n) {
    int w = (blockIdx.x * blockDim.x + threadIdx.x) >> 5;
    int lane = threadIdx.x & 31;
    if (w >= n) return;
    const float2* g = (const float2*)g_t2;
    float2 acc = g[(size_t)w * 32 + lane];  // self loop
    int e = g_rowptr[w], end = g_rowptr[w + 1];
    for (; e + 4 <= end; e += 4) {
        int s0 = g_col[e], s1 = g_col[e + 1], s2 = g_col[e + 2], s3 = g_col[e + 3];
        float2 v0 = g[(size_t)s0 * 32 + lane];
        float2 v1 = g[(size_t)s1 * 32 + lane];
        float2 v2 = g[(size_t)s2 * 32 + lane];
        float2 v3 = g[(size_t)s3 * 32 + lane];
        acc.x += v0.x + v1.x + v2.x + v3.x;
        acc.y += v0.y + v1.y + v2.y + v3.y;
    }
    for (; e < end; e++) {
        int s = g_col[e];
        float2 v = g[(size_t)s * 32 + lane];
        acc.x += v.x; acc.y += v.y;
    }
    float di = g_dinv[w];
    float2 b = ((const float2*)b2)[lane];
    float hx = fmaf(acc.x, di, b.x);
    float hy = fmaf(acc.y, di, b.y);

    // rule_out = h @ We + be (We: [64,3] row-major); lane holds cols 2*lane, 2*lane+1
    int c0 = 2 * lane;
    float p0 = hx * We[c0 * 3 + 0] + hy * We[c0 * 3 + 3];
    float p1 = hx * We[c0 * 3 + 1] + hy * We[c0 * 3 + 4];
    float p2 = hx * We[c0 * 3 + 2] + hy * We[c0 * 3 + 5];
#pragma unroll
    for (int off = 16; off; off >>= 1) {
        p0 += __shfl_xor_sync(0xffffffff, p0, off);
        p1 += __shfl_xor_sync(0xffffffff, p1, off);
        p2 += __shfl_xor_sync(0xffffffff, p2, off);
    }
    float r0 = p0 + be[0], r1 = p1 + be[1], r2 = p2 + be[2];
    float z = r0 * Wg[0] + r1 * Wg[1] + r2 * Wg[2] + bg[0];
    float gate = 1.0f / (1.0f + expf(-z));
    float add = gate * rw[0];
    hx += add;
    hy += add;

    // log_softmax over the 64 features
    float m = fmaxf(hx, hy);
#pragma unroll
    for (int off = 16; off; off >>= 1) m = fmaxf(m, __shfl_xor_sync(0xffffffff, m, off));
    float se = expf(hx - m) + expf(hy - m);
#pragma unroll
    for (int off = 16; off; off >>= 1) se += __shfl_xor_sync(0xffffffff, se, off);
    float ls = logf(se);

    float2 o;
    o.x = hx - m - ls;
    o.y = hy - m - ls;
    ((float2*)out)[(size_t)w * 32 + lane] = o;
}

// ---------------- launch ----------------
extern "C" void kernel_launch(void* const* d_in, const int* in_sizes, int n_in,
                              void* d_out, int out_size) {
    const float* x   = (const float*)d_in[0];
    const int*   ei  = (const int*)d_in[1];   // int32 or int64 raw words; detected on device
    // d_in[2] = rules (unused by the math)
    const float* W1 = (const float*)d_in[3];
    const float* b1 = (const float*)d_in[4];
    const float* W2 = (const float*)d_in[5];
    const float* b2 = (const float*)d_in[6];
    const float* We = (const float*)d_in[7];
    const float* be = (const float*)d_in[8];
    const float* Wg = (const float*)d_in[9];
    const float* bg = (const float*)d_in[10];
    const float* rw = (const float*)d_in[11];

    int n = in_sizes[0] / IN_DIM;
    int E = in_sizes[1] / 2;
    int nb = (n + 255) / 256;   // scan blocks (<= 256 for n <= 65536)

    // CSR build (shared by both layers)
    detect_kernel<<<1, 256>>>(ei, E);
    zero_cnt_kernel<<<(n + 255) / 256, 256>>>(n);
    convert_hist_kernel<<<(E + 255) / 256, 256>>>(ei, E);
    scan_phase1<<<nb, 256>>>(n);
    scan_phase2<<<1, 256>>>(nb);
    scan_phase3<<<(n + 255) / 256, 256>>>(n, E);
    scatter_kernel<<<(E + 255) / 256, 256>>>(E);

    // layer 1
    gemm_scaled<128, 128, 16, 8, 8, 0><<<(n + 127) / 128, 256>>>(x, W1, n, IN_DIM, HID);
    agg1_kernel<<<(n * 32 + 255) / 256, 256>>>(b1, n);

    // layer 2
    gemm_scaled<128, 64, 16, 8, 8, 1><<<(n + 127) / 128, 128>>>(nullptr, W2, n, HID, OUTD);

    // aggregation + rule head + log_softmax fused
    agg2_final_kernel<<<(n * 32 + 255) / 256, 256>>>(b2, We, be, Wg, bg, rw, (float*)d_out, n);
}

// round 5
// speedup vs baseline: 1.4472x; 1.0109x over previous
#include <cuda_runtime.h>
#include <math.h>

#define IN_DIM 256
#define HID 128
#define OUTD 64
#define NMAX 50176
#define EMAX 800000

// ---------------- scratch (static device globals; no allocation) ----------------
__device__ int g_is64;                 // 1 if edge_index is int64, 0 if int32
__device__ __align__(16) int   g_src[EMAX];
__device__ __align__(16) int   g_dst[EMAX];
__device__ __align__(16) int   g_cnt[NMAX];
__device__ __align__(16) int   g_locpre[NMAX];   // block-local exclusive prefix
__device__ __align__(16) int   g_bsum[256];      // per-block sums
__device__ __align__(16) int   g_boff[256];      // scanned block offsets
__device__ __align__(16) int   g_rowptr[NMAX + 1];
__device__ __align__(16) int   g_cursor[NMAX];
__device__ __align__(16) int   g_col[EMAX];
__device__ __align__(16) float g_dinv[NMAX];
__device__ __align__(16) float g_t1[(size_t)NMAX * HID];   // x@W1 (unscaled)
__device__ __align__(16) float g_h1[(size_t)NMAX * HID];   // relu(gcn1)
__device__ __align__(16) float g_t2[(size_t)NMAX * OUTD];  // h1@W2 (unscaled)

// ---------------- edge width detection ----------------
// int64 little-endian with values < 2^31 => every odd 32-bit word is zero.
__global__ void detect_kernel(const int* __restrict__ raw, int E) {
    __shared__ int s_nz;
    if (threadIdx.x == 0) s_nz = 0;
    __syncthreads();
    int i = threadIdx.x;
    if (i < E && raw[2 * i + 1] != 0) atomicOr(&s_nz, 1);
    __syncthreads();
    if (threadIdx.x == 0) g_is64 = (s_nz == 0) ? 1 : 0;
}

__global__ void zero_cnt_kernel(int n) {
    int i = blockIdx.x * blockDim.x + threadIdx.x;
    if (i < n) g_cnt[i] = 0;
}

// convert edges to int32 src/dst arrays + histogram of dst
__global__ void convert_hist_kernel(const int* __restrict__ raw, int E) {
    int i = blockIdx.x * blockDim.x + threadIdx.x;
    if (i >= E) return;
    int s, d;
    if (g_is64) {
        s = raw[2 * i];
        d = raw[2 * E + 2 * i];
    } else {
        s = raw[i];
        d = raw[E + i];
    }
    g_src[i] = s;
    g_dst[i] = d;
    atomicAdd(&g_cnt[d], 1);
}

// ---------------- multi-block exclusive scan (3 phases) ----------------
__global__ void scan_phase1(int n) {
    __shared__ int sh[256];
    int t = threadIdx.x;
    int i = blockIdx.x * 256 + t;
    int v = (i < n) ? g_cnt[i] : 0;
    sh[t] = v;
    __syncthreads();
#pragma unroll
    for (int off = 1; off < 256; off <<= 1) {
        int u = (t >= off) ? sh[t - off] : 0;
        __syncthreads();
        sh[t] += u;
        __syncthreads();
    }
    if (i < n) g_locpre[i] = sh[t] - v;   // exclusive
    if (t == 255) g_bsum[blockIdx.x] = sh[255];
}

__global__ void scan_phase2(int nb) {
    __shared__ int sh[256];
    int t = threadIdx.x;
    int v = (t < nb) ? g_bsum[t] : 0;
    sh[t] = v;
    __syncthreads();
#pragma unroll
    for (int off = 1; off < 256; off <<= 1) {
        int u = (t >= off) ? sh[t - off] : 0;
        __syncthreads();
        sh[t] += u;
        __syncthreads();
    }
    if (t < nb) g_boff[t] = sh[t] - v;
}

__global__ void scan_phase3(int n, int E) {
    int i = blockIdx.x * blockDim.x + threadIdx.x;
    if (i < n) {
        int rp = g_boff[i >> 8] + g_locpre[i];
        g_rowptr[i] = rp;
        g_cursor[i] = rp;
        g_dinv[i]   = rsqrtf((float)g_cnt[i] + 1.0f);  // +1 self loop
    }
    if (i == 0) g_rowptr[n] = E;
}

__global__ void scatter_kernel(int E) {
    int i = blockIdx.x * blockDim.x + threadIdx.x;
    if (i < E) {
        int pos = atomicAdd(&g_cursor[g_dst[i]], 1);
        g_col[pos] = g_src[i];
    }
}

// ---------------- tiled SIMT fp32 GEMM (NO dinv epilogue; graph-independent) ----
// LAYER==0: A = A_in (x), C = g_t1.  LAYER==1: A = g_h1, C = g_t2.
template <int BM, int BN, int BK, int TM, int TN, int LAYER>
__global__ void gemm_plain(const float* __restrict__ A_in, const float* __restrict__ B,
                           int M, int K, int N) {
    const float* __restrict__ A = (LAYER == 0) ? A_in : g_h1;
    float* __restrict__ C       = (LAYER == 0) ? g_t1 : g_t2;

    constexpr int THREADS = (BM / TM) * (BN / TN);
    __shared__ float As[BK][BM + 4];
    __shared__ float Bs[BK][BN + 4];

    int tid = threadIdx.x;
    int tx = tid % (BN / TN);
    int ty = tid / (BN / TN);
    int row0 = blockIdx.x * BM;

    float acc[TM][TN];
#pragma unroll
    for (int i = 0; i < TM; i++)
#pragma unroll
        for (int j = 0; j < TN; j++) acc[i][j] = 0.0f;

    for (int kt = 0; kt < K; kt += BK) {
        constexpr int A4 = BM * BK / 4;
#pragma unroll
        for (int l = tid; l < A4; l += THREADS) {
            int r = l / (BK / 4);
            int kq = l % (BK / 4);
            float4 v = make_float4(0.f, 0.f, 0.f, 0.f);
            int row = row0 + r;
            if (row < M) v = *(const float4*)&A[(size_t)row * K + kt + kq * 4];
            As[kq * 4 + 0][r] = v.x;
            As[kq * 4 + 1][r] = v.y;
            As[kq * 4 + 2][r] = v.z;
            As[kq * 4 + 3][r] = v.w;
        }
        constexpr int B4 = BK * BN / 4;
#pragma unroll
        for (int l = tid; l < B4; l += THREADS) {
            int k = l / (BN / 4);
            int cq = l % (BN / 4);
            *(float4*)&Bs[k][cq * 4] = *(const float4*)&B[(size_t)(kt + k) * N + cq * 4];
        }
        __syncthreads();
#pragma unroll
        for (int k = 0; k < BK; k++) {
            float ra[TM], rb[TN];
#pragma unroll
            for (int i = 0; i < TM; i++) ra[i] = As[k][ty * TM + i];
#pragma unroll
            for (int j = 0; j < TN; j++) rb[j] = Bs[k][tx * TN + j];
#pragma unroll
            for (int i = 0; i < TM; i++)
#pragma unroll
                for (int j = 0; j < TN; j++) acc[i][j] = fmaf(ra[i], rb[j], acc[i][j]);
        }
        __syncthreads();
    }

#pragma unroll
    for (int i = 0; i < TM; i++) {
        int row = row0 + ty * TM + i;
        if (row < M) {
#pragma unroll
            for (int j = 0; j < TN; j += 4) {
                float4 v;
                v.x = acc[i][j + 0];
                v.y = acc[i][j + 1];
                v.z = acc[i][j + 2];
                v.w = acc[i][j + 3];
                *(float4*)&C[(size_t)row * N + tx * TN + j] = v;
            }
        }
    }
}

// ---------------- layer-1 aggregation: warp per node, 128 features ----------------
// t1 holds unscaled x@W1. acc = t1[w]*dinv[w] (self) + sum t1[s]*dinv[s]; then *dinv[w].
__global__ void agg1_kernel(const float* __restrict__ b1, int n) {
    int w = (blockIdx.x * blockDim.x + threadIdx.x) >> 5;
    int lane = threadIdx.x & 31;
    if (w >= n) return;
    const float4* g = (const float4*)g_t1;
    float di = g_dinv[w];
    float4 self = g[(size_t)w * 32 + lane];
    float4 acc;
    acc.x = self.x * di; acc.y = self.y * di; acc.z = self.z * di; acc.w = self.w * di;
    int e = g_rowptr[w], end = g_rowptr[w + 1];
    for (; e + 4 <= end; e += 4) {
        int s0 = g_col[e], s1 = g_col[e + 1], s2 = g_col[e + 2], s3 = g_col[e + 3];
        float d0 = g_dinv[s0], d1 = g_dinv[s1], d2 = g_dinv[s2], d3 = g_dinv[s3];
        float4 v0 = g[(size_t)s0 * 32 + lane];
        float4 v1 = g[(size_t)s1 * 32 + lane];
        float4 v2 = g[(size_t)s2 * 32 + lane];
        float4 v3 = g[(size_t)s3 * 32 + lane];
        acc.x = fmaf(v0.x, d0, fmaf(v1.x, d1, fmaf(v2.x, d2, fmaf(v3.x, d3, acc.x))));
        acc.y = fmaf(v0.y, d0, fmaf(v1.y, d1, fmaf(v2.y, d2, fmaf(v3.y, d3, acc.y))));
        acc.z = fmaf(v0.z, d0, fmaf(v1.z, d1, fmaf(v2.z, d2, fmaf(v3.z, d3, acc.z))));
        acc.w = fmaf(v0.w, d0, fmaf(v1.w, d1, fmaf(v2.w, d2, fmaf(v3.w, d3, acc.w))));
    }
    for (; e < end; e++) {
        int s = g_col[e];
        float ds = g_dinv[s];
        float4 v = g[(size_t)s * 32 + lane];
        acc.x = fmaf(v.x, ds, acc.x);
        acc.y = fmaf(v.y, ds, acc.y);
        acc.z = fmaf(v.z, ds, acc.z);
        acc.w = fmaf(v.w, ds, acc.w);
    }
    float4 b = ((const float4*)b1)[lane];
    float4 r;
    r.x = fmaxf(fmaf(acc.x, di, b.x), 0.f);
    r.y = fmaxf(fmaf(acc.y, di, b.y), 0.f);
    r.z = fmaxf(fmaf(acc.z, di, b.z), 0.f);
    r.w = fmaxf(fmaf(acc.w, di, b.w), 0.f);
    ((float4*)g_h1)[(size_t)w * 32 + lane] = r;
}

// ---------------- layer-2 aggregation + rule head + log_softmax ----------------
__global__ void agg2_final_kernel(const float* __restrict__ b2,
                                  const float* __restrict__ We,
                                  const float* __restrict__ be,
                                  const float* __restrict__ Wg,
                                  const float* __restrict__ bg,
                                  const float* __restrict__ rw,
                                  float* __restrict__ out, int n) {
    int w = (blockIdx.x * blockDim.x + threadIdx.x) >> 5;
    int lane = threadIdx.x & 31;
    if (w >= n) return;
    const float2* g = (const float2*)g_t2;
    float di = g_dinv[w];
    float2 self = g[(size_t)w * 32 + lane];
    float2 acc;
    acc.x = self.x * di; acc.y = self.y * di;
    int e = g_rowptr[w], end = g_rowptr[w + 1];
    for (; e + 4 <= end; e += 4) {
        int s0 = g_col[e], s1 = g_col[e + 1], s2 = g_col[e + 2], s3 = g_col[e + 3];
        float d0 = g_dinv[s0], d1 = g_dinv[s1], d2 = g_dinv[s2], d3 = g_dinv[s3];
        float2 v0 = g[(size_t)s0 * 32 + lane];
        float2 v1 = g[(size_t)s1 * 32 + lane];
        float2 v2 = g[(size_t)s2 * 32 + lane];
        float2 v3 = g[(size_t)s3 * 32 + lane];
        acc.x = fmaf(v0.x, d0, fmaf(v1.x, d1, fmaf(v2.x, d2, fmaf(v3.x, d3, acc.x))));
        acc.y = fmaf(v0.y, d0, fmaf(v1.y, d1, fmaf(v2.y, d2, fmaf(v3.y, d3, acc.y))));
    }
    for (; e < end; e++) {
        int s = g_col[e];
        float ds = g_dinv[s];
        float2 v = g[(size_t)s * 32 + lane];
        acc.x = fmaf(v.x, ds, acc.x);
        acc.y = fmaf(v.y, ds, acc.y);
    }
    float2 b = ((const float2*)b2)[lane];
    float hx = fmaf(acc.x, di, b.x);
    float hy = fmaf(acc.y, di, b.y);

    // rule_out = h @ We + be (We: [64,3] row-major); lane holds cols 2*lane, 2*lane+1
    int c0 = 2 * lane;
    float p0 = hx * We[c0 * 3 + 0] + hy * We[c0 * 3 + 3];
    float p1 = hx * We[c0 * 3 + 1] + hy * We[c0 * 3 + 4];
    float p2 = hx * We[c0 * 3 + 2] + hy * We[c0 * 3 + 5];
#pragma unroll
    for (int off = 16; off; off >>= 1) {
        p0 += __shfl_xor_sync(0xffffffff, p0, off);
        p1 += __shfl_xor_sync(0xffffffff, p1, off);
        p2 += __shfl_xor_sync(0xffffffff, p2, off);
    }
    float r0 = p0 + be[0], r1 = p1 + be[1], r2 = p2 + be[2];
    float z = r0 * Wg[0] + r1 * Wg[1] + r2 * Wg[2] + bg[0];
    float gate = 1.0f / (1.0f + expf(-z));
    float add = gate * rw[0];
    hx += add;
    hy += add;

    // log_softmax over the 64 features
    float m = fmaxf(hx, hy);
#pragma unroll
    for (int off = 16; off; off >>= 1) m = fmaxf(m, __shfl_xor_sync(0xffffffff, m, off));
    float se = expf(hx - m) + expf(hy - m);
#pragma unroll
    for (int off = 16; off; off >>= 1) se += __shfl_xor_sync(0xffffffff, se, off);
    float ls = logf(se);

    float2 o;
    o.x = hx - m - ls;
    o.y = hy - m - ls;
    ((float2*)out)[(size_t)w * 32 + lane] = o;
}

// ---------------- launch (fork-join: CSR chain overlaps GEMM1) ----------------
extern "C" void kernel_launch(void* const* d_in, const int* in_sizes, int n_in,
                              void* d_out, int out_size) {
    const float* x   = (const float*)d_in[0];
    const int*   ei  = (const int*)d_in[1];   // int32 or int64 raw words; detected on device
    // d_in[2] = rules (unused by the math)
    const float* W1 = (const float*)d_in[3];
    const float* b1 = (const float*)d_in[4];
    const float* W2 = (const float*)d_in[5];
    const float* b2 = (const float*)d_in[6];
    const float* We = (const float*)d_in[7];
    const float* be = (const float*)d_in[8];
    const float* Wg = (const float*)d_in[9];
    const float* bg = (const float*)d_in[10];
    const float* rw = (const float*)d_in[11];

    int n = in_sizes[0] / IN_DIM;
    int E = in_sizes[1] / 2;
    int nb = (n + 255) / 256;   // scan blocks (<= 256 for n <= 65536)

    cudaStream_t s2;
    cudaStreamCreate(&s2);
    cudaEvent_t evFork, evJoin;
    cudaEventCreateWithFlags(&evFork, cudaEventDisableTiming);
    cudaEventCreateWithFlags(&evJoin, cudaEventDisableTiming);

    // fork: side stream runs the CSR build while GEMM1 runs on the main stream
    cudaEventRecord(evFork, 0);
    cudaStreamWaitEvent(s2, evFork, 0);

    detect_kernel<<<1, 256, 0, s2>>>(ei, E);
    zero_cnt_kernel<<<(n + 255) / 256, 256, 0, s2>>>(n);
    convert_hist_kernel<<<(E + 255) / 256, 256, 0, s2>>>(ei, E);
    scan_phase1<<<nb, 256, 0, s2>>>(n);
    scan_phase2<<<1, 256, 0, s2>>>(nb);
    scan_phase3<<<(n + 255) / 256, 256, 0, s2>>>(n, E);
    scatter_kernel<<<(E + 255) / 256, 256, 0, s2>>>(E);

    // layer-1 GEMM (graph-independent now)
    gemm_plain<128, 128, 16, 8, 8, 0><<<(n + 127) / 128, 256>>>(x, W1, n, IN_DIM, HID);

    // join
    cudaEventRecord(evJoin, s2);
    cudaStreamWaitEvent(0, evJoin, 0);

    agg1_kernel<<<(n * 32 + 255) / 256, 256>>>(b1, n);
    gemm_plain<128, 64, 16, 8, 8, 1><<<(n + 127) / 128, 128>>>(nullptr, W2, n, HID, OUTD);
    agg2_final_kernel<<<(n * 32 + 255) / 256, 256>>>(b2, We, be, Wg, bg, rw, (float*)d_out, n);

    cudaEventDestroy(evFork);
    cudaEventDestroy(evJoin);
    cudaStreamDestroy(s2);
}